// round 2
// baseline (speedup 1.0000x reference)
#include <cuda_runtime.h>

#define BATCH 4
#define CH    128
#define CIN   256
#define HH    224
#define WW    224
#define HW    50176
#define NCLS  41
#define KTOT  2304   // 256 * 9

// ---------------- scratch (static device globals; no allocs) ----------------
static __device__ float g_xcat[(size_t)BATCH * CIN * HW];  // [b][ci][p] concat(add,mul)
static __device__ float g_fuse[(size_t)BATCH * CH * HW];   // conv output
static __device__ float g_wT[KTOT * CH];                   // transposed weights [k][oc]
static __device__ float g_sum_d[BATCH * NCLS * CH];
static __device__ float g_sum_f[BATCH * NCLS * CH];
static __device__ float g_cnt[BATCH * NCLS];
static __device__ float g_scale[2 * BATCH * CH];           // [which(0=d,1=f)][b][c]

__device__ __forceinline__ float sigmoid_fast(float x) {
    return 1.f / (1.f + __expf(-x));
}

// ---------------- prep: add / mul into concat buffer (float4) ----------------
__global__ void prep_kernel(const float* __restrict__ r, const float* __restrict__ dd) {
    int idx = blockIdx.x * 256 + threadIdx.x;
    const int n4 = BATCH * CH * HW / 4;
    if (idx >= n4) return;
    int i = idx * 4;
    int b = i / (CH * HW);
    int rem = i - b * (CH * HW);
    float4 rv = *reinterpret_cast<const float4*>(r + i);
    float4 dv = *reinterpret_cast<const float4*>(dd + i);
    float4 add, mul;
    add.x = rv.x + dv.x; add.y = rv.y + dv.y; add.z = rv.z + dv.z; add.w = rv.w + dv.w;
    mul.x = rv.x * sigmoid_fast(dv.x);
    mul.y = rv.y * sigmoid_fast(dv.y);
    mul.z = rv.z * sigmoid_fast(dv.z);
    mul.w = rv.w * sigmoid_fast(dv.w);
    float* base = g_xcat + (size_t)b * CIN * HW;
    *reinterpret_cast<float4*>(base + rem) = add;
    *reinterpret_cast<float4*>(base + (size_t)CH * HW + rem) = mul;
}

// ---------------- weight transpose: w[oc][k] -> wT[k][oc] ----------------
__global__ void wtrans_kernel(const float* __restrict__ w) {
    int i = blockIdx.x * 256 + threadIdx.x;
    if (i >= KTOT * CH) return;
    int oc = i & (CH - 1);
    int k  = i >> 7;
    g_wT[i] = w[(size_t)oc * KTOT + k];
}

// ---------------- zero accumulators (must run every launch) ----------------
__global__ void zero_kernel() {
    int i = blockIdx.x * 256 + threadIdx.x;
    if (i < BATCH * NCLS * CH) { g_sum_d[i] = 0.f; g_sum_f[i] = 0.f; }
    if (i < BATCH * NCLS) g_cnt[i] = 0.f;
}

// ---------------- RA segment stats (shared-memory privatized bins) ----------------
// mode 0: feats = dfeats (d tensor), sums = g_sum_d, also counts
// mode 1: feats = g_fuse,            sums = g_sum_f
__global__ void ra_stats_kernel(const float* __restrict__ dfeats,
                                const int* __restrict__ label, int mode) {
    __shared__ float bins[NCLS * 129];   // pad 129: bank = (lab + c) % 32
    __shared__ float cnts[NCLS];
    __shared__ int   slab[1024];

    const float* feats = mode ? g_fuse : dfeats;
    float* sums = mode ? g_sum_f : g_sum_d;

    const int b   = blockIdx.y;
    const int p0  = blockIdx.x * 1024;
    const int tid = threadIdx.x;

    for (int i = tid; i < NCLS * 129; i += 256) bins[i] = 0.f;
    if (tid < NCLS) cnts[tid] = 0.f;
    for (int i = tid; i < 1024; i += 256) {
        int p = p0 + i;
        int y = p / WW;
        int x = p - y * WW;
        slab[i] = label[(size_t)b * 896 * 896 + (size_t)(4 * y) * 896 + 4 * x];
    }
    __syncthreads();

    if (mode == 0) {
        for (int i = tid; i < 1024; i += 256) atomicAdd(&cnts[slab[i]], 1.f);
    }
    for (int c = 0; c < CH; c++) {
        const float* fp = feats + ((size_t)b * CH + c) * HW + p0;
        #pragma unroll
        for (int i = tid; i < 1024; i += 256) {
            atomicAdd(&bins[slab[i] * 129 + c], fp[i]);
        }
    }
    __syncthreads();

    for (int i = tid; i < NCLS * CH; i += 256) {
        int k = i >> 7;
        int c = i & (CH - 1);
        atomicAdd(&sums[((size_t)b * NCLS + k) * CH + c], bins[k * 129 + c]);
    }
    if (mode == 0 && tid < NCLS) atomicAdd(&g_cnt[b * NCLS + tid], cnts[tid]);
}

// ---------------- RA finalize: means -> norm -> MLP -> sigmoid scales ----------------
__global__ void ra_finalize_kernel(const float* __restrict__ w1_d, const float* __restrict__ w2_d,
                                   const float* __restrict__ w1_f, const float* __restrict__ w2_f) {
    const int which = blockIdx.x & 1;
    const int b     = blockIdx.x >> 1;
    const float* sums = which ? g_sum_f : g_sum_d;
    const float* w1   = which ? w1_f : w1_d;
    const float* w2   = which ? w2_f : w2_d;

    __shared__ float att[CH];
    __shared__ float hid[8];
    const int c = threadIdx.x;  // 128 threads

    float s1 = 0.f, s2 = 0.f;
    for (int k = 0; k < NCLS; k++) {
        float cnt = g_cnt[b * NCLS + k];
        float m = sums[((size_t)b * NCLS + k) * CH + c] / fmaxf(cnt, 1.f);
        s1 += m;
        s2 += m * m;
    }
    float nrm = fmaxf(sqrtf(s2), 1e-12f);
    att[c] = s1 / nrm;
    __syncthreads();

    if (c < 8) {
        float h = 0.f;
        for (int j = 0; j < CH; j++) h += att[j] * w1[c * CH + j];
        hid[c] = fmaxf(h, 0.f);
    }
    __syncthreads();

    float o = 0.f;
    #pragma unroll
    for (int j = 0; j < 8; j++) o += hid[j] * w2[c * 8 + j];
    g_scale[(which * BATCH + b) * CH + c] = 1.f / (1.f + expf(-o));
}

// ---------------- 3x3 conv as implicit SGEMM with packed fma.rn.f32x2 ----------------
// Per block: 128 pixels x 128 output channels, K-loop over 2304 in chunks of 16.
// Thread tile 8x8 (oc x pixel); pixel pairs packed in 64-bit regs for f32x2 FMA.
__global__ __launch_bounds__(256, 2) void conv_kernel() {
    __shared__ float As[16][128];   // [kk][pixel]
    __shared__ float Bs[16][128];   // [kk][oc]

    const int tid  = threadIdx.x;
    const int b    = blockIdx.y;
    const int p0   = blockIdx.x * 128;
    const int tx   = tid & 15;    // pixel group  (8 pixels)
    const int ty   = tid >> 4;    // oc group     (8 ocs)
    const int lpix = tid & 127;   // loader: pixel / oc index
    const int lk   = tid >> 7;    // loader: k parity (0/1)

    const int p  = p0 + lpix;
    const int py = p / WW;
    const int px = p - py * WW;
    const float* __restrict__ xb = g_xcat + (size_t)b * CIN * HW;

    unsigned long long acc[8][4];
    #pragma unroll
    for (int i = 0; i < 8; i++)
        #pragma unroll
        for (int j = 0; j < 4; j++) acc[i][j] = 0ull;

    for (int k0 = 0; k0 < KTOT; k0 += 16) {
        #pragma unroll
        for (int j = 0; j < 8; j++) {
            int kk = j * 2 + lk;
            int k  = k0 + kk;
            int ci = k / 9;
            int f  = k - ci * 9;
            int fy = f / 3;
            int fx = f - fy * 3;
            int iy = py + fy - 1;
            int ix = px + fx - 1;
            float v = 0.f;
            if (iy >= 0 && iy < HH && ix >= 0 && ix < WW)
                v = xb[ci * HW + iy * WW + ix];
            As[kk][lpix] = v;
            Bs[kk][lpix] = g_wT[(k0 + kk) * CH + lpix];
        }
        __syncthreads();

        #pragma unroll
        for (int kk = 0; kk < 16; kk++) {
            ulonglong2 A0 = *reinterpret_cast<const ulonglong2*>(&As[kk][tx * 8]);
            ulonglong2 A1 = *reinterpret_cast<const ulonglong2*>(&As[kk][tx * 8 + 4]);
            unsigned long long a2[4] = {A0.x, A0.y, A1.x, A1.y};
            uint4 B0 = *reinterpret_cast<const uint4*>(&Bs[kk][ty * 8]);
            uint4 B1 = *reinterpret_cast<const uint4*>(&Bs[kk][ty * 8 + 4]);
            unsigned int bsv[8] = {B0.x, B0.y, B0.z, B0.w, B1.x, B1.y, B1.z, B1.w};
            #pragma unroll
            for (int io = 0; io < 8; io++) {
                unsigned long long b2;
                asm("mov.b64 %0, {%1, %1};" : "=l"(b2) : "r"(bsv[io]));
                #pragma unroll
                for (int ip = 0; ip < 4; ip++) {
                    asm("fma.rn.f32x2 %0, %1, %2, %0;"
                        : "+l"(acc[io][ip]) : "l"(b2), "l"(a2[ip]));
                }
            }
        }
        __syncthreads();
    }

    float* fb = g_fuse + (size_t)b * CH * HW;
    #pragma unroll
    for (int io = 0; io < 8; io++) {
        int oc = ty * 8 + io;
        float4 v0, v1;
        v0.x = __uint_as_float((unsigned)(acc[io][0]));
        v0.y = __uint_as_float((unsigned)(acc[io][0] >> 32));
        v0.z = __uint_as_float((unsigned)(acc[io][1]));
        v0.w = __uint_as_float((unsigned)(acc[io][1] >> 32));
        v1.x = __uint_as_float((unsigned)(acc[io][2]));
        v1.y = __uint_as_float((unsigned)(acc[io][2] >> 32));
        v1.z = __uint_as_float((unsigned)(acc[io][3]));
        v1.w = __uint_as_float((unsigned)(acc[io][3] >> 32));
        *reinterpret_cast<float4*>(fb + (size_t)oc * HW + p0 + tx * 8)     = v0;
        *reinterpret_cast<float4*>(fb + (size_t)oc * HW + p0 + tx * 8 + 4) = v1;
    }
}

// ---------------- final: out = fuse*scale_f + d*scale_d ----------------
__global__ void final_kernel(const float* __restrict__ dd, float* __restrict__ out) {
    int idx = blockIdx.x * 256 + threadIdx.x;
    const int n4 = BATCH * CH * HW / 4;
    if (idx >= n4) return;
    int i = idx * 4;
    int bc = i / HW;
    int b = bc >> 7;
    int c = bc & (CH - 1);
    float sd = g_scale[b * CH + c];
    float sf = g_scale[(BATCH + b) * CH + c];
    float4 dv = *reinterpret_cast<const float4*>(dd + i);
    float4 fv = *reinterpret_cast<const float4*>(g_fuse + i);
    float4 o;
    o.x = fv.x * sf + dv.x * sd;
    o.y = fv.y * sf + dv.y * sd;
    o.z = fv.z * sf + dv.z * sd;
    o.w = fv.w * sf + dv.w * sd;
    *reinterpret_cast<float4*>(out + i) = o;
}

// ---------------- launcher ----------------
extern "C" void kernel_launch(void* const* d_in, const int* in_sizes, int n_in,
                              void* d_out, int out_size) {
    const float* r      = (const float*)d_in[0];
    const float* d      = (const float*)d_in[1];
    const int*   label  = (const int*)  d_in[2];
    const float* w_fuse = (const float*)d_in[3];
    const float* w1_d   = (const float*)d_in[4];
    const float* w2_d   = (const float*)d_in[5];
    const float* w1_f   = (const float*)d_in[6];
    const float* w2_f   = (const float*)d_in[7];
    float* out = (float*)d_out;

    const int n4 = BATCH * CH * HW / 4;

    prep_kernel<<<(n4 + 255) / 256, 256>>>(r, d);
    wtrans_kernel<<<(KTOT * CH + 255) / 256, 256>>>(w_fuse);
    zero_kernel<<<(BATCH * NCLS * CH + 255) / 256, 256>>>();

    ra_stats_kernel<<<dim3(HW / 1024, BATCH), 256>>>(d, label, 0);

    conv_kernel<<<dim3(HW / 128, BATCH), 256>>>();

    ra_stats_kernel<<<dim3(HW / 1024, BATCH), 256>>>(d, label, 1);

    ra_finalize_kernel<<<2 * BATCH, CH>>>(w1_d, w2_d, w1_f, w2_f);

    final_kernel<<<(n4 + 255) / 256, 256>>>(d, out);
}

// round 4
// speedup vs baseline: 2.8411x; 2.8411x over previous
#include <cuda_runtime.h>
#include <cuda_bf16.h>
#include <cstdint>

#define BATCH 4
#define CH    128
#define CIN   256
#define HH    224
#define WW    224
#define HW    50176
#define NCLS  41

// ---------------------------------------------------------------------------
// scratch (static device globals; no allocs)
// ---------------------------------------------------------------------------
static __device__ uint32_t g_xpack[(size_t)BATCH * CIN * HW];  // (hi|lo) bf16 pairs of concat(add,mul)
static __device__ float    g_fuse[(size_t)BATCH * CH * HW];    // conv output fp32
static __device__ uint4    g_bt4[36 * 2048];                   // per chunk: hi tile 16KB + lo tile 16KB (SW128 images)
static __device__ float    g_sum_d[BATCH * NCLS * CH];
static __device__ float    g_sum_f[BATCH * NCLS * CH];
static __device__ float    g_cnt[BATCH * NCLS];
static __device__ float    g_scale[2 * BATCH * CH];

__device__ __forceinline__ float sigmoid_fast(float x) { return 1.f / (1.f + __expf(-x)); }

__device__ __forceinline__ uint32_t pack_bf(float x) {
    __nv_bfloat16 h = __float2bfloat16(x);
    float r = x - __bfloat162float(h);
    __nv_bfloat16 l = __float2bfloat16(r);
    return (uint32_t)__bfloat16_as_ushort(h) | ((uint32_t)__bfloat16_as_ushort(l) << 16);
}

__device__ __forceinline__ uint32_t smem_u32(const void* p) {
    uint32_t a;
    asm("{ .reg .u64 t; cvta.to.shared.u64 t, %1; cvt.u32.u64 %0, t; }" : "=r"(a) : "l"(p));
    return a;
}

__device__ __forceinline__ void ldsm4(uint32_t* r, uint32_t addr) {
    asm volatile("ldmatrix.sync.aligned.m8n8.x4.shared.b16 {%0,%1,%2,%3}, [%4];"
                 : "=r"(r[0]), "=r"(r[1]), "=r"(r[2]), "=r"(r[3]) : "r"(addr));
}

__device__ __forceinline__ void mma16816(float* c, const uint32_t* a, const uint32_t* b) {
    asm volatile(
        "mma.sync.aligned.m16n8k16.row.col.f32.bf16.bf16.f32 "
        "{%0,%1,%2,%3}, {%4,%5,%6,%7}, {%8,%9}, {%0,%1,%2,%3};"
        : "+f"(c[0]), "+f"(c[1]), "+f"(c[2]), "+f"(c[3])
        : "r"(a[0]), "r"(a[1]), "r"(a[2]), "r"(a[3]), "r"(b[0]), "r"(b[1]));
}

// ---------------- prep: add / mul -> packed bf16-pair planes ----------------
__global__ void prep_kernel(const float* __restrict__ r, const float* __restrict__ dd) {
    int idx = blockIdx.x * 256 + threadIdx.x;
    const int n4 = BATCH * CH * HW / 4;
    if (idx >= n4) return;
    int i = idx * 4;
    int b = i / (CH * HW);
    int rem = i - b * (CH * HW);
    float4 rv = *reinterpret_cast<const float4*>(r + i);
    float4 dv = *reinterpret_cast<const float4*>(dd + i);
    uint4 addp, mulp;
    addp.x = pack_bf(rv.x + dv.x);
    addp.y = pack_bf(rv.y + dv.y);
    addp.z = pack_bf(rv.z + dv.z);
    addp.w = pack_bf(rv.w + dv.w);
    mulp.x = pack_bf(rv.x * sigmoid_fast(dv.x));
    mulp.y = pack_bf(rv.y * sigmoid_fast(dv.y));
    mulp.z = pack_bf(rv.z * sigmoid_fast(dv.z));
    mulp.w = pack_bf(rv.w * sigmoid_fast(dv.w));
    uint32_t* base = g_xpack + (size_t)b * CIN * HW;
    *reinterpret_cast<uint4*>(base + rem) = addp;
    *reinterpret_cast<uint4*>(base + (size_t)CH * HW + rem) = mulp;
}

// ---------------- weight prepack: SW128 SMEM-image B tiles ----------------
// tile t = (f*4+cc)*2+v : 128 oc rows x 64 k bf16, SW128 image, 16KB each
__global__ void wprep_kernel(const float* __restrict__ w) {
    int idx = blockIdx.x * 256 + threadIdx.x;
    if (idx >= 36 * 2 * CH * 64) return;
    int kk = idx & 63;
    int oc = (idx >> 6) & 127;
    int t  = idx >> 13;          // 0..71
    int v  = t & 1;
    int cc = (t >> 1) & 3;
    int f  = t >> 3;
    int ci = cc * 64 + kk;
    float wv = w[(size_t)(oc * CIN + ci) * 9 + f];
    __nv_bfloat16 hi = __float2bfloat16(wv);
    __nv_bfloat16 val = (v == 0) ? hi : __float2bfloat16(wv - __bfloat162float(hi));
    uint32_t off = ((uint32_t)oc << 7) + (((uint32_t)kk * 2) ^ (((uint32_t)oc & 7) << 4));
    *(__nv_bfloat16*)((char*)g_bt4 + (size_t)t * 16384 + off) = val;
}

// ---------------- zero accumulators ----------------
__global__ void zero_kernel() {
    int i = blockIdx.x * 256 + threadIdx.x;
    if (i < BATCH * NCLS * CH) { g_sum_d[i] = 0.f; g_sum_f[i] = 0.f; }
    if (i < BATCH * NCLS) g_cnt[i] = 0.f;
}

// ---------------- RA segment stats (channel-group split, z = 4 groups) ----------------
__global__ void ra_stats_kernel(const float* __restrict__ dfeats,
                                const int* __restrict__ label, int mode) {
    __shared__ float bins[NCLS * 33];
    __shared__ float cnts[NCLS];
    __shared__ int   slab[1024];

    const float* feats = mode ? g_fuse : dfeats;
    float* sums = mode ? g_sum_f : g_sum_d;

    const int b   = blockIdx.y;
    const int p0  = blockIdx.x * 1024;
    const int c0  = blockIdx.z * 32;
    const int tid = threadIdx.x;

    for (int i = tid; i < NCLS * 33; i += 256) bins[i] = 0.f;
    if (tid < NCLS) cnts[tid] = 0.f;
    for (int i = tid; i < 1024; i += 256) {
        int p = p0 + i;
        int y = p / WW;
        int x = p - y * WW;
        slab[i] = label[(size_t)b * 896 * 896 + (size_t)(4 * y) * 896 + 4 * x];
    }
    __syncthreads();

    if (mode == 0 && blockIdx.z == 0) {
        for (int i = tid; i < 1024; i += 256) atomicAdd(&cnts[slab[i]], 1.f);
    }
    for (int c = 0; c < 32; c++) {
        const float* fp = feats + ((size_t)b * CH + c0 + c) * HW + p0;
        for (int i = tid; i < 1024; i += 256) {
            atomicAdd(&bins[slab[i] * 33 + c], fp[i]);
        }
    }
    __syncthreads();

    for (int i = tid; i < NCLS * 32; i += 256) {
        int k = i >> 5;
        int c = i & 31;
        atomicAdd(&sums[((size_t)b * NCLS + k) * CH + c0 + c], bins[k * 33 + c]);
    }
    if (mode == 0 && blockIdx.z == 0 && tid < NCLS) atomicAdd(&g_cnt[b * NCLS + tid], cnts[tid]);
}

// ---------------- RA finalize ----------------
__global__ void ra_finalize_kernel(const float* __restrict__ w1_d, const float* __restrict__ w2_d,
                                   const float* __restrict__ w1_f, const float* __restrict__ w2_f) {
    const int which = blockIdx.x & 1;
    const int b     = blockIdx.x >> 1;
    const float* sums = which ? g_sum_f : g_sum_d;
    const float* w1   = which ? w1_f : w1_d;
    const float* w2   = which ? w2_f : w2_d;

    __shared__ float att[CH];
    __shared__ float hid[8];
    const int c = threadIdx.x;  // 128 threads

    float s1 = 0.f, s2 = 0.f;
    for (int k = 0; k < NCLS; k++) {
        float cnt = g_cnt[b * NCLS + k];
        float m = sums[((size_t)b * NCLS + k) * CH + c] / fmaxf(cnt, 1.f);
        s1 += m;
        s2 += m * m;
    }
    float nrm = fmaxf(sqrtf(s2), 1e-12f);
    att[c] = s1 / nrm;
    __syncthreads();

    if (c < 8) {
        float h = 0.f;
        for (int j = 0; j < CH; j++) h += att[j] * w1[c * CH + j];
        hid[c] = fmaxf(h, 0.f);
    }
    __syncthreads();

    float o = 0.f;
    #pragma unroll
    for (int j = 0; j < 8; j++) o += hid[j] * w2[c * 8 + j];
    g_scale[(which * BATCH + b) * CH + c] = 1.f / (1.f + expf(-o));
}

// ---------------- conv via mma.sync bf16 (3-term hi/lo split) ----------------
// CTA: 128 pixels x 128 oc.  36 chunks = 9 taps x 4 ci-blocks of 64 channels.
// SMEM: Ahi(16K) Alo(16K) Bhi(16K) Blo(16K) = 64KB, SW128 swizzle everywhere.
// 8 warps in 2(M) x 4(N): warp tile 64 pixels x 32 oc.
#define CONV_SMEM 65536

__global__ __launch_bounds__(256, 2) void conv_mma_kernel() {
    extern __shared__ __align__(1024) char smem[];
    const uint32_t sb = smem_u32(smem);
    const int tid  = threadIdx.x;
    const int wid  = tid >> 5;
    const int lane = tid & 31;
    const int b    = blockIdx.y;
    const int p0   = blockIdx.x * 128;

    const int wm = wid & 1;        // M warp (0..1) -> 64 pixels
    const int wn = wid >> 1;       // N warp (0..3) -> 32 oc
    const int rln  = lane & 7;
    const int quad = lane >> 3;

    // ldmatrix lane address components (A: row-major m16k16; B: [oc][k])
    const int a_row_off = rln + ((quad & 1) << 3);
    const uint32_t a_kb = (uint32_t)(quad >> 1) << 4;
    const int b_oc_off  = rln + ((quad >> 1) << 3);
    const uint32_t b_kb = (uint32_t)(quad & 1) << 4;
    const uint32_t lxor = (uint32_t)rln << 4;

    const uint32_t sAhi = sb;
    const uint32_t sBhi = sb + 32768;
    const uint32_t aBase = sAhi + (uint32_t)(wm * 64 + a_row_off) * 128;
    const uint32_t bBase = sBhi + (uint32_t)(wn * 32 + b_oc_off) * 128;

    // loader mapping: 2 threads per pixel row
    const int row  = tid >> 1;
    const int half = tid & 1;
    const int p    = p0 + row;
    const int py   = p / WW;
    const int px   = p - py * WW;
    const uint32_t swx = (uint32_t)(row & 7) << 4;
    char* aRowHi = smem + row * 128;
    char* aRowLo = smem + 16384 + row * 128;

    float acc[4][4][4];
    #pragma unroll
    for (int i = 0; i < 4; i++)
        #pragma unroll
        for (int j = 0; j < 4; j++)
            #pragma unroll
            for (int k = 0; k < 4; k++) acc[i][j][k] = 0.f;

    for (int c = 0; c < 36; c++) {
        const int f  = c >> 2;
        const int cc = c & 3;
        const int fy = f / 3;
        const int iy = py + fy - 1;
        const int ix = px + (f - fy * 3) - 1;
        const bool valid = ((unsigned)iy < (unsigned)HH) && ((unsigned)ix < (unsigned)WW);
        const uint32_t* sp = g_xpack + ((size_t)(b * CIN + cc * 64 + half * 32)) * HW
                                     + (iy * WW + ix);

        // A tile: split packed (hi|lo) into two planes, swizzled uint4 stores
        #pragma unroll
        for (int q = 0; q < 4; q++) {
            uint32_t xs[8];
            #pragma unroll
            for (int e = 0; e < 8; e++)
                xs[e] = valid ? sp[(size_t)(8 * q + e) * HW] : 0u;
            uint4 hp, lp;
            hp.x = (xs[0] & 0xFFFFu) | (xs[1] << 16);  lp.x = (xs[0] >> 16) | (xs[1] & 0xFFFF0000u);
            hp.y = (xs[2] & 0xFFFFu) | (xs[3] << 16);  lp.y = (xs[2] >> 16) | (xs[3] & 0xFFFF0000u);
            hp.z = (xs[4] & 0xFFFFu) | (xs[5] << 16);  lp.z = (xs[4] >> 16) | (xs[5] & 0xFFFF0000u);
            hp.w = (xs[6] & 0xFFFFu) | (xs[7] << 16);  lp.w = (xs[6] >> 16) | (xs[7] & 0xFFFF0000u);
            uint32_t co = ((uint32_t)(64 * half + 16 * q)) ^ swx;
            *(uint4*)(aRowHi + co) = hp;
            *(uint4*)(aRowLo + co) = lp;
        }

        // B tile: 32KB linear copy of pre-swizzled hi+lo images
        {
            const uint4* bsrc = g_bt4 + (size_t)c * 2048;
            uint4* bdst = (uint4*)(smem + 32768);
            #pragma unroll
            for (int i = 0; i < 8; i++) bdst[i * 256 + tid] = bsrc[i * 256 + tid];
        }
        __syncthreads();

        #pragma unroll
        for (int ks = 0; ks < 4; ks++) {
            uint32_t Ahi[4][4], Alo[4][4];
            const uint32_t aco = ((uint32_t)(ks * 32) + a_kb) ^ lxor;
            #pragma unroll
            for (int mf = 0; mf < 4; mf++) {
                ldsm4(Ahi[mf], aBase + mf * 2048 + aco);
                ldsm4(Alo[mf], aBase + 16384 + mf * 2048 + aco);
            }
            const uint32_t bco = ((uint32_t)(ks * 32) + b_kb) ^ lxor;
            #pragma unroll
            for (int ng = 0; ng < 2; ng++) {
                uint32_t Bh[4], Bl[4];
                ldsm4(Bh, bBase + ng * 2048 + bco);
                ldsm4(Bl, bBase + 16384 + ng * 2048 + bco);
                #pragma unroll
                for (int mf = 0; mf < 4; mf++) {
                    float* a0 = acc[mf][ng * 2];
                    float* a1 = acc[mf][ng * 2 + 1];
                    mma16816(a0, Ahi[mf], Bh);
                    mma16816(a0, Ahi[mf], Bl);
                    mma16816(a0, Alo[mf], Bh);
                    mma16816(a1, Ahi[mf], Bh + 2);
                    mma16816(a1, Ahi[mf], Bl + 2);
                    mma16816(a1, Alo[mf], Bh + 2);
                }
            }
        }
        __syncthreads();
    }

    // epilogue: c-frag -> g_fuse[oc][pixel]
    float* fb = g_fuse + (size_t)b * CH * HW;
    const int prow = p0 + wm * 64 + (lane >> 2);
    const int oc0  = wn * 32 + (lane & 3) * 2;
    #pragma unroll
    for (int mf = 0; mf < 4; mf++) {
        #pragma unroll
        for (int nf = 0; nf < 4; nf++) {
            const int pix = prow + mf * 16;
            const int oc  = oc0 + nf * 8;
            fb[(size_t)oc * HW + pix]           = acc[mf][nf][0];
            fb[(size_t)(oc + 1) * HW + pix]     = acc[mf][nf][1];
            fb[(size_t)oc * HW + pix + 8]       = acc[mf][nf][2];
            fb[(size_t)(oc + 1) * HW + pix + 8] = acc[mf][nf][3];
        }
    }
}

// ---------------- final: out = fuse*scale_f + d*scale_d ----------------
__global__ void final_kernel(const float* __restrict__ dd, float* __restrict__ out) {
    int idx = blockIdx.x * 256 + threadIdx.x;
    const int n4 = BATCH * CH * HW / 4;
    if (idx >= n4) return;
    int i = idx * 4;
    int bc = i / HW;
    int b = bc >> 7;
    int c = bc & (CH - 1);
    float sd = g_scale[b * CH + c];
    float sf = g_scale[(BATCH + b) * CH + c];
    float4 dv = *reinterpret_cast<const float4*>(dd + i);
    float4 fv = *reinterpret_cast<const float4*>(g_fuse + i);
    float4 o;
    o.x = fv.x * sf + dv.x * sd;
    o.y = fv.y * sf + dv.y * sd;
    o.z = fv.z * sf + dv.z * sd;
    o.w = fv.w * sf + dv.w * sd;
    *reinterpret_cast<float4*>(out + i) = o;
}

// ---------------- launcher ----------------
extern "C" void kernel_launch(void* const* d_in, const int* in_sizes, int n_in,
                              void* d_out, int out_size) {
    const float* r      = (const float*)d_in[0];
    const float* d      = (const float*)d_in[1];
    const int*   label  = (const int*)  d_in[2];
    const float* w_fuse = (const float*)d_in[3];
    const float* w1_d   = (const float*)d_in[4];
    const float* w2_d   = (const float*)d_in[5];
    const float* w1_f   = (const float*)d_in[6];
    const float* w2_f   = (const float*)d_in[7];
    float* out = (float*)d_out;

    static int smem_set = 0;
    if (!smem_set) {
        cudaFuncSetAttribute(conv_mma_kernel, cudaFuncAttributeMaxDynamicSharedMemorySize, CONV_SMEM);
        smem_set = 1;
    }

    const int n4 = BATCH * CH * HW / 4;

    prep_kernel<<<(n4 + 255) / 256, 256>>>(r, d);
    wprep_kernel<<<(36 * 2 * CH * 64 + 255) / 256, 256>>>(w_fuse);
    zero_kernel<<<(BATCH * NCLS * CH + 255) / 256, 256>>>();

    ra_stats_kernel<<<dim3(HW / 1024, BATCH, 4), 256>>>(d, label, 0);

    conv_mma_kernel<<<dim3(HW / 128, BATCH), 256, CONV_SMEM>>>();

    ra_stats_kernel<<<dim3(HW / 1024, BATCH, 4), 256>>>(d, label, 1);

    ra_finalize_kernel<<<2 * BATCH, CH>>>(w1_d, w2_d, w1_f, w2_f);

    final_kernel<<<(n4 + 255) / 256, 256>>>(d, out);
}

// round 5
// speedup vs baseline: 3.0492x; 1.0733x over previous
#include <cuda_runtime.h>
#include <cuda_bf16.h>
#include <cstdint>

#define BATCH 4
#define CH    128
#define CIN   256
#define HH    224
#define WW    224
#define HW    50176
#define NCLS  41

// ---------------------------------------------------------------------------
// scratch (static device globals; no allocs)
// ---------------------------------------------------------------------------
static __device__ uint32_t g_xpack[(size_t)BATCH * CIN * HW];  // (hi|lo) bf16 pairs of concat(add,mul)
static __device__ float    g_fuse[(size_t)BATCH * CH * HW];    // conv output fp32
static __device__ uint4    g_bt4[36 * 2048];                   // per chunk: hi tile 16KB + lo tile 16KB (SW128 images)
static __device__ float    g_sum_d[BATCH * NCLS * CH];
static __device__ float    g_sum_f[BATCH * NCLS * CH];
static __device__ float    g_cnt[BATCH * NCLS];
static __device__ float    g_scale[2 * BATCH * CH];

__device__ __forceinline__ float sigmoid_fast(float x) { return 1.f / (1.f + __expf(-x)); }

__device__ __forceinline__ uint32_t pack_bf(float x) {
    __nv_bfloat16 h = __float2bfloat16(x);
    float r = x - __bfloat162float(h);
    __nv_bfloat16 l = __float2bfloat16(r);
    return (uint32_t)__bfloat16_as_ushort(h) | ((uint32_t)__bfloat16_as_ushort(l) << 16);
}

__device__ __forceinline__ uint32_t smem_u32(const void* p) {
    uint32_t a;
    asm("{ .reg .u64 t; cvta.to.shared.u64 t, %1; cvt.u32.u64 %0, t; }" : "=r"(a) : "l"(p));
    return a;
}

__device__ __forceinline__ void ldsm4(uint32_t* r, uint32_t addr) {
    asm volatile("ldmatrix.sync.aligned.m8n8.x4.shared.b16 {%0,%1,%2,%3}, [%4];"
                 : "=r"(r[0]), "=r"(r[1]), "=r"(r[2]), "=r"(r[3]) : "r"(addr));
}

__device__ __forceinline__ void mma16816(float* c, const uint32_t* a, const uint32_t* b) {
    asm volatile(
        "mma.sync.aligned.m16n8k16.row.col.f32.bf16.bf16.f32 "
        "{%0,%1,%2,%3}, {%4,%5,%6,%7}, {%8,%9}, {%0,%1,%2,%3};"
        : "+f"(c[0]), "+f"(c[1]), "+f"(c[2]), "+f"(c[3])
        : "r"(a[0]), "r"(a[1]), "r"(a[2]), "r"(a[3]), "r"(b[0]), "r"(b[1]));
}

#define CP_ASYNC16(dst, src) \
    asm volatile("cp.async.cg.shared.global [%0], [%1], 16;" :: "r"(dst), "l"(src) : "memory")
#define CP_COMMIT() asm volatile("cp.async.commit_group;" ::: "memory")
#define CP_WAIT0()  asm volatile("cp.async.wait_group 0;" ::: "memory")

// ---------------- zero accumulators ----------------
__global__ void zero_kernel() {
    int i = blockIdx.x * 256 + threadIdx.x;
    if (i < BATCH * NCLS * CH) { g_sum_d[i] = 0.f; g_sum_f[i] = 0.f; }
    if (i < BATCH * NCLS) g_cnt[i] = 0.f;
}

// ---------------- weight prepack: SW128 SMEM-image B tiles ----------------
__global__ void wprep_kernel(const float* __restrict__ w) {
    int idx = blockIdx.x * 256 + threadIdx.x;
    if (idx >= 36 * 2 * CH * 64) return;
    int kk = idx & 63;
    int oc = (idx >> 6) & 127;
    int t  = idx >> 13;          // 0..71
    int v  = t & 1;
    int cc = (t >> 1) & 3;
    int f  = t >> 3;
    int ci = cc * 64 + kk;
    float wv = w[(size_t)(oc * CIN + ci) * 9 + f];
    __nv_bfloat16 hi = __float2bfloat16(wv);
    __nv_bfloat16 val = (v == 0) ? hi : __float2bfloat16(wv - __bfloat162float(hi));
    uint32_t off = ((uint32_t)oc << 7) + (((uint32_t)kk * 2) ^ (((uint32_t)oc & 7) << 4));
    *(__nv_bfloat16*)((char*)g_bt4 + (size_t)t * 16384 + off) = val;
}

// ---------------- prep + RA(d) fused ----------------
// grid (HW/1024, nb, 4); block 256. Each block: 1024 pixels x 32 channels.
__global__ void prep_ra_kernel(const float* __restrict__ r, const float* __restrict__ dd,
                               const int* __restrict__ label, int b0) {
    __shared__ float bins[NCLS * 33];
    __shared__ float cnts[NCLS];
    __shared__ int   slab[1024];

    const int b   = b0 + blockIdx.y;
    const int c0  = blockIdx.z * 32;
    const int p0  = blockIdx.x * 1024;
    const int tid = threadIdx.x;

    for (int i = tid; i < NCLS * 33; i += 256) bins[i] = 0.f;
    if (tid < NCLS) cnts[tid] = 0.f;
    for (int i = tid; i < 1024; i += 256) {
        int p = p0 + i;
        int y = p / WW;
        int x = p - y * WW;
        slab[i] = label[(size_t)b * 896 * 896 + (size_t)(4 * y) * 896 + 4 * x];
    }
    __syncthreads();

    if (blockIdx.z == 0) {
        for (int i = tid; i < 1024; i += 256) atomicAdd(&cnts[slab[i]], 1.f);
    }

    const int i4 = tid * 4;
    const int l0 = slab[i4], l1 = slab[i4 + 1], l2 = slab[i4 + 2], l3 = slab[i4 + 3];
    uint32_t* xb = g_xpack + (size_t)b * CIN * HW;

    for (int c = 0; c < 32; c++) {
        size_t off = ((size_t)(b * CH + c0 + c)) * HW + p0 + i4;
        float4 rv = *reinterpret_cast<const float4*>(r + off);
        float4 dv = *reinterpret_cast<const float4*>(dd + off);

        atomicAdd(&bins[l0 * 33 + c], dv.x);
        atomicAdd(&bins[l1 * 33 + c], dv.y);
        atomicAdd(&bins[l2 * 33 + c], dv.z);
        atomicAdd(&bins[l3 * 33 + c], dv.w);

        uint4 ap, mp;
        ap.x = pack_bf(rv.x + dv.x);
        ap.y = pack_bf(rv.y + dv.y);
        ap.z = pack_bf(rv.z + dv.z);
        ap.w = pack_bf(rv.w + dv.w);
        mp.x = pack_bf(rv.x * sigmoid_fast(dv.x));
        mp.y = pack_bf(rv.y * sigmoid_fast(dv.y));
        mp.z = pack_bf(rv.z * sigmoid_fast(dv.z));
        mp.w = pack_bf(rv.w * sigmoid_fast(dv.w));
        *reinterpret_cast<uint4*>(xb + ((size_t)(c0 + c)) * HW + p0 + i4)      = ap;
        *reinterpret_cast<uint4*>(xb + ((size_t)(CH + c0 + c)) * HW + p0 + i4) = mp;
    }
    __syncthreads();

    for (int i = tid; i < NCLS * 32; i += 256) {
        int k = i >> 5;
        int c = i & 31;
        atomicAdd(&g_sum_d[((size_t)b * NCLS + k) * CH + c0 + c], bins[k * 33 + c]);
    }
    if (blockIdx.z == 0 && tid < NCLS) atomicAdd(&g_cnt[b * NCLS + tid], cnts[tid]);
}

// ---------------- RA finalize ----------------
__global__ void ra_finalize_kernel(const float* __restrict__ w1_d, const float* __restrict__ w2_d,
                                   const float* __restrict__ w1_f, const float* __restrict__ w2_f) {
    const int which = blockIdx.x & 1;
    const int b     = blockIdx.x >> 1;
    const float* sums = which ? g_sum_f : g_sum_d;
    const float* w1   = which ? w1_f : w1_d;
    const float* w2   = which ? w2_f : w2_d;

    __shared__ float att[CH];
    __shared__ float hid[8];
    const int c = threadIdx.x;  // 128 threads

    float s1 = 0.f, s2 = 0.f;
    for (int k = 0; k < NCLS; k++) {
        float cnt = g_cnt[b * NCLS + k];
        float m = sums[((size_t)b * NCLS + k) * CH + c] / fmaxf(cnt, 1.f);
        s1 += m;
        s2 += m * m;
    }
    float nrm = fmaxf(sqrtf(s2), 1e-12f);
    att[c] = s1 / nrm;
    __syncthreads();

    if (c < 8) {
        float h = 0.f;
        for (int j = 0; j < CH; j++) h += att[j] * w1[c * CH + j];
        hid[c] = fmaxf(h, 0.f);
    }
    __syncthreads();

    float o = 0.f;
    #pragma unroll
    for (int j = 0; j < 8; j++) o += hid[j] * w2[c * 8 + j];
    g_scale[(which * BATCH + b) * CH + c] = 1.f / (1.f + expf(-o));
}

// ---------------- conv via mma.sync bf16 (3-term hi/lo split) + fused RA(fuse) ----------------
// CTA: 128 pixels x 128 oc.  36 chunks = 9 taps x 4 ci-blocks of 64 channels.
// SMEM: Ahi(16K) Alo(16K) Bhi(16K) Blo(16K) = 64KB; epilogue overlays bins[41*129]+labels.
#define CONV_SMEM 65536

__global__ __launch_bounds__(256, 2) void conv_mma_kernel(const int* __restrict__ label) {
    extern __shared__ __align__(1024) char smem[];
    const uint32_t sb = smem_u32(smem);
    const int tid  = threadIdx.x;
    const int wid  = tid >> 5;
    const int lane = tid & 31;
    const int b    = blockIdx.y;
    const int p0   = blockIdx.x * 128;

    const int wm = wid & 1;        // M warp (0..1) -> 64 pixels
    const int wn = wid >> 1;       // N warp (0..3) -> 32 oc
    const int rln  = lane & 7;
    const int quad = lane >> 3;

    const int a_row_off = rln + ((quad & 1) << 3);
    const uint32_t a_kb = (uint32_t)(quad >> 1) << 4;
    const int b_oc_off  = rln + ((quad >> 1) << 3);
    const uint32_t b_kb = (uint32_t)(quad & 1) << 4;
    const uint32_t lxor = (uint32_t)rln << 4;

    const uint32_t aBase = sb + (uint32_t)(wm * 64 + a_row_off) * 128;
    const uint32_t bBase = sb + 32768 + (uint32_t)(wn * 32 + b_oc_off) * 128;

    // loader mapping: 2 threads per pixel row
    const int row  = tid >> 1;
    const int half = tid & 1;
    const int p    = p0 + row;
    const int py   = p / WW;
    const int px   = p - py * WW;
    const uint32_t swx = (uint32_t)(row & 7) << 4;
    char* aRowHi = smem + row * 128;
    char* aRowLo = smem + 16384 + row * 128;

    float acc[4][4][4];
    #pragma unroll
    for (int i = 0; i < 4; i++)
        #pragma unroll
        for (int j = 0; j < 4; j++)
            #pragma unroll
            for (int k = 0; k < 4; k++) acc[i][j][k] = 0.f;

    for (int c = 0; c < 36; c++) {
        const int f  = c >> 2;
        const int cc = c & 3;
        const int fy = f / 3;
        const int iy = py + fy - 1;
        const int ix = px + (f - fy * 3) - 1;
        const bool valid = ((unsigned)iy < (unsigned)HH) && ((unsigned)ix < (unsigned)WW);
        const uint32_t* sp = g_xpack + ((size_t)(b * CIN + cc * 64 + half * 32)) * HW
                                     + (iy * WW + ix);

        // B tile: async 32KB linear copy of pre-swizzled hi+lo images
        {
            const char* bsrc = (const char*)(g_bt4 + (size_t)c * 2048) + tid * 16;
            uint32_t bdst = sb + 32768 + tid * 16;
            #pragma unroll
            for (int i = 0; i < 8; i++) CP_ASYNC16(bdst + i * 4096, bsrc + i * 4096);
            CP_COMMIT();
        }

        // A tile: split packed (hi|lo) into two planes, swizzled uint4 stores
        #pragma unroll
        for (int q = 0; q < 4; q++) {
            uint32_t xs[8];
            #pragma unroll
            for (int e = 0; e < 8; e++)
                xs[e] = valid ? sp[(size_t)(8 * q + e) * HW] : 0u;
            uint4 hp, lp;
            hp.x = (xs[0] & 0xFFFFu) | (xs[1] << 16);  lp.x = (xs[0] >> 16) | (xs[1] & 0xFFFF0000u);
            hp.y = (xs[2] & 0xFFFFu) | (xs[3] << 16);  lp.y = (xs[2] >> 16) | (xs[3] & 0xFFFF0000u);
            hp.z = (xs[4] & 0xFFFFu) | (xs[5] << 16);  lp.z = (xs[4] >> 16) | (xs[5] & 0xFFFF0000u);
            hp.w = (xs[6] & 0xFFFFu) | (xs[7] << 16);  lp.w = (xs[6] >> 16) | (xs[7] & 0xFFFF0000u);
            uint32_t co = ((uint32_t)(64 * half + 16 * q)) ^ swx;
            *(uint4*)(aRowHi + co) = hp;
            *(uint4*)(aRowLo + co) = lp;
        }

        CP_WAIT0();
        __syncthreads();

        #pragma unroll
        for (int ks = 0; ks < 4; ks++) {
            uint32_t Ahi[4][4], Alo[4][4];
            const uint32_t aco = ((uint32_t)(ks * 32) + a_kb) ^ lxor;
            #pragma unroll
            for (int mf = 0; mf < 4; mf++) {
                ldsm4(Ahi[mf], aBase + mf * 2048 + aco);
                ldsm4(Alo[mf], aBase + 16384 + mf * 2048 + aco);
            }
            const uint32_t bco = ((uint32_t)(ks * 32) + b_kb) ^ lxor;
            #pragma unroll
            for (int ng = 0; ng < 2; ng++) {
                uint32_t Bh[4], Bl[4];
                ldsm4(Bh, bBase + ng * 2048 + bco);
                ldsm4(Bl, bBase + 16384 + ng * 2048 + bco);
                #pragma unroll
                for (int mf = 0; mf < 4; mf++) {
                    float* a0 = acc[mf][ng * 2];
                    float* a1 = acc[mf][ng * 2 + 1];
                    mma16816(a0, Ahi[mf], Bh);
                    mma16816(a0, Ahi[mf], Bl);
                    mma16816(a0, Alo[mf], Bh);
                    mma16816(a1, Ahi[mf], Bh + 2);
                    mma16816(a1, Ahi[mf], Bl + 2);
                    mma16816(a1, Alo[mf], Bh + 2);
                }
            }
        }
        __syncthreads();
    }

    // ---- fused epilogue: write g_fuse + RA(fuse) bins ----
    float* bins = (float*)smem;                    // 41*129 floats = 21156 B
    int*   slb  = (int*)(smem + 21248);            // 128 labels
    for (int i = tid; i < NCLS * 129; i += 256) bins[i] = 0.f;
    if (tid < 128) {
        int pp = p0 + tid;
        int yy = pp / WW;
        int xx = pp - yy * WW;
        slb[tid] = label[(size_t)b * 896 * 896 + (size_t)(4 * yy) * 896 + 4 * xx];
    }
    __syncthreads();

    float* fb = g_fuse + (size_t)b * CH * HW;
    const int prl = wm * 64 + (lane >> 2);         // pixel-in-block (row 0)
    const int oc0 = wn * 32 + (lane & 3) * 2;
    #pragma unroll
    for (int mf = 0; mf < 4; mf++) {
        const int px0 = prl + mf * 16;
        const int la  = slb[px0];
        const int lb2 = slb[px0 + 8];
        #pragma unroll
        for (int nf = 0; nf < 4; nf++) {
            const int oc = oc0 + nf * 8;
            float v0 = acc[mf][nf][0], v1 = acc[mf][nf][1];
            float v2 = acc[mf][nf][2], v3 = acc[mf][nf][3];
            fb[(size_t)oc * HW + p0 + px0]           = v0;
            fb[(size_t)(oc + 1) * HW + p0 + px0]     = v1;
            fb[(size_t)oc * HW + p0 + px0 + 8]       = v2;
            fb[(size_t)(oc + 1) * HW + p0 + px0 + 8] = v3;
            atomicAdd(&bins[la * 129 + oc], v0);
            atomicAdd(&bins[la * 129 + oc + 1], v1);
            atomicAdd(&bins[lb2 * 129 + oc], v2);
            atomicAdd(&bins[lb2 * 129 + oc + 1], v3);
        }
    }
    __syncthreads();
    for (int i = tid; i < NCLS * CH; i += 256) {
        int k = i >> 7;
        int c = i & 127;
        atomicAdd(&g_sum_f[((size_t)b * NCLS + k) * CH + c], bins[k * 129 + c]);
    }
}

// ---------------- final: out = fuse*scale_f + d*scale_d ----------------
__global__ void final_kernel(const float* __restrict__ dd, float* __restrict__ out) {
    int idx = blockIdx.x * 256 + threadIdx.x;
    const int n4 = BATCH * CH * HW / 4;
    if (idx >= n4) return;
    int i = idx * 4;
    int bc = i / HW;
    int b = bc >> 7;
    int c = bc & (CH - 1);
    float sd = g_scale[b * CH + c];
    float sf = g_scale[(BATCH + b) * CH + c];
    float4 dv = *reinterpret_cast<const float4*>(dd + i);
    float4 fv = *reinterpret_cast<const float4*>(g_fuse + i);
    float4 o;
    o.x = fv.x * sf + dv.x * sd;
    o.y = fv.y * sf + dv.y * sd;
    o.z = fv.z * sf + dv.z * sd;
    o.w = fv.w * sf + dv.w * sd;
    *reinterpret_cast<float4*>(out + i) = o;
}

// ---------------- launcher ----------------
extern "C" void kernel_launch(void* const* d_in, const int* in_sizes, int n_in,
                              void* d_out, int out_size) {
    const float* r      = (const float*)d_in[0];
    const float* d      = (const float*)d_in[1];
    const int*   label  = (const int*)  d_in[2];
    const float* w_fuse = (const float*)d_in[3];
    const float* w1_d   = (const float*)d_in[4];
    const float* w2_d   = (const float*)d_in[5];
    const float* w1_f   = (const float*)d_in[6];
    const float* w2_f   = (const float*)d_in[7];
    float* out = (float*)d_out;

    static int smem_set = 0;
    if (!smem_set) {
        cudaFuncSetAttribute(conv_mma_kernel, cudaFuncAttributeMaxDynamicSharedMemorySize, CONV_SMEM);
        smem_set = 1;
    }

    const int n4 = BATCH * CH * HW / 4;

    zero_kernel<<<(BATCH * NCLS * CH + 255) / 256, 256>>>();                       // 1
    wprep_kernel<<<(36 * 2 * CH * 64 + 255) / 256, 256>>>(w_fuse);                 // 2

    prep_ra_kernel<<<dim3(HW / 1024, 1, 4), 256>>>(r, d, label, 0);                // 3
    prep_ra_kernel<<<dim3(HW / 1024, 1, 4), 256>>>(r, d, label, 1);                // 4
    prep_ra_kernel<<<dim3(HW / 1024, 2, 4), 256>>>(r, d, label, 2);                // 5

    conv_mma_kernel<<<dim3(HW / 128, BATCH), 256, CONV_SMEM>>>(label);             // 6 (ncu lands here)

    ra_finalize_kernel<<<2 * BATCH, CH>>>(w1_d, w2_d, w1_f, w2_f);                 // 7
    final_kernel<<<(n4 + 255) / 256, 256>>>(d, out);                               // 8
}

// round 6
// speedup vs baseline: 3.3788x; 1.1081x over previous
#include <cuda_runtime.h>
#include <cuda_bf16.h>
#include <cstdint>

#define BATCH 4
#define CH    128
#define CIN   256
#define HH    224
#define WW    224
#define HW    50176
#define NCLS  41

// ---------------------------------------------------------------------------
// scratch (static device globals; no allocs)
// ---------------------------------------------------------------------------
static __device__ uint32_t g_xpack[(size_t)BATCH * CIN * HW];  // (hi|lo) bf16 pairs of concat(add,mul)
static __device__ float    g_fuse[(size_t)BATCH * CH * HW];    // conv output fp32
static __device__ uint4    g_bt4[36 * 2048];                   // per chunk: hi tile 16KB + lo tile 16KB (SW128 images)
static __device__ float    g_sum_d[BATCH * NCLS * CH];
static __device__ float    g_sum_f[BATCH * NCLS * CH];
static __device__ float    g_cnt[BATCH * NCLS];
static __device__ float    g_scale[2 * BATCH * CH];

__device__ __forceinline__ float sigmoid_fast(float x) { return 1.f / (1.f + __expf(-x)); }

__device__ __forceinline__ uint32_t pack_bf(float x) {
    __nv_bfloat16 h = __float2bfloat16(x);
    float r = x - __bfloat162float(h);
    __nv_bfloat16 l = __float2bfloat16(r);
    return (uint32_t)__bfloat16_as_ushort(h) | ((uint32_t)__bfloat16_as_ushort(l) << 16);
}

__device__ __forceinline__ uint32_t smem_u32(const void* p) {
    uint32_t a;
    asm("{ .reg .u64 t; cvta.to.shared.u64 t, %1; cvt.u32.u64 %0, t; }" : "=r"(a) : "l"(p));
    return a;
}

__device__ __forceinline__ void ldsm4(uint32_t* r, uint32_t addr) {
    asm volatile("ldmatrix.sync.aligned.m8n8.x4.shared.b16 {%0,%1,%2,%3}, [%4];"
                 : "=r"(r[0]), "=r"(r[1]), "=r"(r[2]), "=r"(r[3]) : "r"(addr));
}

__device__ __forceinline__ void mma16816(float* c, const uint32_t* a, const uint32_t* b) {
    asm volatile(
        "mma.sync.aligned.m16n8k16.row.col.f32.bf16.bf16.f32 "
        "{%0,%1,%2,%3}, {%4,%5,%6,%7}, {%8,%9}, {%0,%1,%2,%3};"
        : "+f"(c[0]), "+f"(c[1]), "+f"(c[2]), "+f"(c[3])
        : "r"(a[0]), "r"(a[1]), "r"(a[2]), "r"(a[3]), "r"(b[0]), "r"(b[1]));
}

#define CP_ASYNC16(dst, src) \
    asm volatile("cp.async.cg.shared.global [%0], [%1], 16;" :: "r"(dst), "l"(src) : "memory")
#define CP_COMMIT() asm volatile("cp.async.commit_group;" ::: "memory")
#define CP_WAIT0()  asm volatile("cp.async.wait_group 0;" ::: "memory")

// ---------------- zero accumulators ----------------
__global__ void zero_kernel() {
    int i = blockIdx.x * 256 + threadIdx.x;
    if (i < BATCH * NCLS * CH) { g_sum_d[i] = 0.f; g_sum_f[i] = 0.f; }
    if (i < BATCH * NCLS) g_cnt[i] = 0.f;
}

// ---------------- weight prepack: SW128 SMEM-image B tiles ----------------
__global__ void wprep_kernel(const float* __restrict__ w) {
    int idx = blockIdx.x * 256 + threadIdx.x;
    if (idx >= 36 * 2 * CH * 64) return;
    int kk = idx & 63;
    int oc = (idx >> 6) & 127;
    int t  = idx >> 13;          // 0..71
    int v  = t & 1;
    int cc = (t >> 1) & 3;
    int f  = t >> 3;
    int ci = cc * 64 + kk;
    float wv = w[(size_t)(oc * CIN + ci) * 9 + f];
    __nv_bfloat16 hi = __float2bfloat16(wv);
    __nv_bfloat16 val = (v == 0) ? hi : __float2bfloat16(wv - __bfloat162float(hi));
    uint32_t off = ((uint32_t)oc << 7) + (((uint32_t)kk * 2) ^ (((uint32_t)oc & 7) << 4));
    *(__nv_bfloat16*)((char*)g_bt4 + (size_t)t * 16384 + off) = val;
}

// ---------------- prep + RA(d) fused ----------------
// grid (HW/1024, BATCH, 4); block 256. Each block: 1024 pixels x 32 channels.
__global__ void prep_ra_kernel(const float* __restrict__ r, const float* __restrict__ dd,
                               const int* __restrict__ label) {
    __shared__ float bins[NCLS * 33];
    __shared__ float cnts[NCLS];
    __shared__ int   slab[1024];

    const int b   = blockIdx.y;
    const int c0  = blockIdx.z * 32;
    const int p0  = blockIdx.x * 1024;
    const int tid = threadIdx.x;

    for (int i = tid; i < NCLS * 33; i += 256) bins[i] = 0.f;
    if (tid < NCLS) cnts[tid] = 0.f;
    for (int i = tid; i < 1024; i += 256) {
        int p = p0 + i;
        int y = p / WW;
        int x = p - y * WW;
        slab[i] = label[(size_t)b * 896 * 896 + (size_t)(4 * y) * 896 + 4 * x];
    }
    __syncthreads();

    if (blockIdx.z == 0) {
        for (int i = tid; i < 1024; i += 256) atomicAdd(&cnts[slab[i]], 1.f);
    }

    const int i4 = tid * 4;
    const int l0 = slab[i4], l1 = slab[i4 + 1], l2 = slab[i4 + 2], l3 = slab[i4 + 3];
    uint32_t* xb = g_xpack + (size_t)b * CIN * HW;

    for (int c = 0; c < 32; c++) {
        size_t off = ((size_t)(b * CH + c0 + c)) * HW + p0 + i4;
        float4 rv = *reinterpret_cast<const float4*>(r + off);
        float4 dv = *reinterpret_cast<const float4*>(dd + off);

        atomicAdd(&bins[l0 * 33 + c], dv.x);
        atomicAdd(&bins[l1 * 33 + c], dv.y);
        atomicAdd(&bins[l2 * 33 + c], dv.z);
        atomicAdd(&bins[l3 * 33 + c], dv.w);

        uint4 ap, mp;
        ap.x = pack_bf(rv.x + dv.x);
        ap.y = pack_bf(rv.y + dv.y);
        ap.z = pack_bf(rv.z + dv.z);
        ap.w = pack_bf(rv.w + dv.w);
        mp.x = pack_bf(rv.x * sigmoid_fast(dv.x));
        mp.y = pack_bf(rv.y * sigmoid_fast(dv.y));
        mp.z = pack_bf(rv.z * sigmoid_fast(dv.z));
        mp.w = pack_bf(rv.w * sigmoid_fast(dv.w));
        *reinterpret_cast<uint4*>(xb + ((size_t)(c0 + c)) * HW + p0 + i4)      = ap;
        *reinterpret_cast<uint4*>(xb + ((size_t)(CH + c0 + c)) * HW + p0 + i4) = mp;
    }
    __syncthreads();

    for (int i = tid; i < NCLS * 32; i += 256) {
        int k = i >> 5;
        int c = i & 31;
        atomicAdd(&g_sum_d[((size_t)b * NCLS + k) * CH + c0 + c], bins[k * 33 + c]);
    }
    if (blockIdx.z == 0 && tid < NCLS) atomicAdd(&g_cnt[b * NCLS + tid], cnts[tid]);
}

// ---------------- RA finalize ----------------
__global__ void ra_finalize_kernel(const float* __restrict__ w1_d, const float* __restrict__ w2_d,
                                   const float* __restrict__ w1_f, const float* __restrict__ w2_f) {
    const int which = blockIdx.x & 1;
    const int b     = blockIdx.x >> 1;
    const float* sums = which ? g_sum_f : g_sum_d;
    const float* w1   = which ? w1_f : w1_d;
    const float* w2   = which ? w2_f : w2_d;

    __shared__ float att[CH];
    __shared__ float hid[8];
    const int c = threadIdx.x;  // 128 threads

    float s1 = 0.f, s2 = 0.f;
    for (int k = 0; k < NCLS; k++) {
        float cnt = g_cnt[b * NCLS + k];
        float m = sums[((size_t)b * NCLS + k) * CH + c] / fmaxf(cnt, 1.f);
        s1 += m;
        s2 += m * m;
    }
    float nrm = fmaxf(sqrtf(s2), 1e-12f);
    att[c] = s1 / nrm;
    __syncthreads();

    if (c < 8) {
        float h = 0.f;
        for (int j = 0; j < CH; j++) h += att[j] * w1[c * CH + j];
        hid[c] = fmaxf(h, 0.f);
    }
    __syncthreads();

    float o = 0.f;
    #pragma unroll
    for (int j = 0; j < 8; j++) o += hid[j] * w2[c * 8 + j];
    g_scale[(which * BATCH + b) * CH + c] = 1.f / (1.f + expf(-o));
}

// ---------------- conv via mma.sync bf16 (3-term hi/lo split) + fused RA(fuse) ----------------
// CTA: 128 pixels x 128 oc.  36 chunks = 9 taps x 4 ci-blocks of 64 channels.
// SMEM: Ahi(16K) Alo(16K) Bhi(16K) Blo(16K) = 64KB; epilogue overlays bins[41*129]+labels.
#define CONV_SMEM 65536

__global__ __launch_bounds__(256, 2) void conv_mma_kernel(const int* __restrict__ label) {
    extern __shared__ __align__(1024) char smem[];
    const uint32_t sb = smem_u32(smem);
    const int tid  = threadIdx.x;
    const int wid  = tid >> 5;
    const int lane = tid & 31;
    const int b    = blockIdx.y;
    const int p0   = blockIdx.x * 128;

    const int wm = wid & 1;        // M warp (0..1) -> 64 pixels
    const int wn = wid >> 1;       // N warp (0..3) -> 32 oc
    const int rln  = lane & 7;
    const int quad = lane >> 3;

    const int a_row_off = rln + ((quad & 1) << 3);
    const uint32_t a_kb = (uint32_t)(quad >> 1) << 4;
    const int b_oc_off  = rln + ((quad >> 1) << 3);
    const uint32_t b_kb = (uint32_t)(quad & 1) << 4;
    const uint32_t lxor = (uint32_t)rln << 4;

    const uint32_t aBase = sb + (uint32_t)(wm * 64 + a_row_off) * 128;
    const uint32_t bBase = sb + 32768 + (uint32_t)(wn * 32 + b_oc_off) * 128;

    // loader mapping: 2 threads per pixel row
    const int row  = tid >> 1;
    const int half = tid & 1;
    const int p    = p0 + row;
    const int py   = p / WW;
    const int px   = p - py * WW;
    const uint32_t swx = (uint32_t)(row & 7) << 4;
    char* aRowHi = smem + row * 128;
    char* aRowLo = smem + 16384 + row * 128;

    float acc[4][4][4];
    #pragma unroll
    for (int i = 0; i < 4; i++)
        #pragma unroll
        for (int j = 0; j < 4; j++)
            #pragma unroll
            for (int k = 0; k < 4; k++) acc[i][j][k] = 0.f;

    for (int c = 0; c < 36; c++) {
        const int f  = c >> 2;
        const int cc = c & 3;
        const int fy = f / 3;
        const int iy = py + fy - 1;
        const int ix = px + (f - fy * 3) - 1;
        const bool valid = ((unsigned)iy < (unsigned)HH) && ((unsigned)ix < (unsigned)WW);
        const uint32_t* sp = g_xpack + ((size_t)(b * CIN + cc * 64 + half * 32)) * HW
                                     + (iy * WW + ix);

        // B tile: async 32KB linear copy of pre-swizzled hi+lo images
        {
            const char* bsrc = (const char*)(g_bt4 + (size_t)c * 2048) + tid * 16;
            uint32_t bdst = sb + 32768 + tid * 16;
            #pragma unroll
            for (int i = 0; i < 8; i++) CP_ASYNC16(bdst + i * 4096, bsrc + i * 4096);
            CP_COMMIT();
        }

        // A tile: split packed (hi|lo) into two planes, swizzled uint4 stores
        #pragma unroll
        for (int q = 0; q < 4; q++) {
            uint32_t xs[8];
            #pragma unroll
            for (int e = 0; e < 8; e++)
                xs[e] = valid ? sp[(size_t)(8 * q + e) * HW] : 0u;
            uint4 hp, lp;
            hp.x = (xs[0] & 0xFFFFu) | (xs[1] << 16);  lp.x = (xs[0] >> 16) | (xs[1] & 0xFFFF0000u);
            hp.y = (xs[2] & 0xFFFFu) | (xs[3] << 16);  lp.y = (xs[2] >> 16) | (xs[3] & 0xFFFF0000u);
            hp.z = (xs[4] & 0xFFFFu) | (xs[5] << 16);  lp.z = (xs[4] >> 16) | (xs[5] & 0xFFFF0000u);
            hp.w = (xs[6] & 0xFFFFu) | (xs[7] << 16);  lp.w = (xs[6] >> 16) | (xs[7] & 0xFFFF0000u);
            uint32_t co = ((uint32_t)(64 * half + 16 * q)) ^ swx;
            *(uint4*)(aRowHi + co) = hp;
            *(uint4*)(aRowLo + co) = lp;
        }

        CP_WAIT0();
        __syncthreads();

        #pragma unroll
        for (int ks = 0; ks < 4; ks++) {
            uint32_t Ahi[4][4], Alo[4][4];
            const uint32_t aco = ((uint32_t)(ks * 32) + a_kb) ^ lxor;
            #pragma unroll
            for (int mf = 0; mf < 4; mf++) {
                ldsm4(Ahi[mf], aBase + mf * 2048 + aco);
                ldsm4(Alo[mf], aBase + 16384 + mf * 2048 + aco);
            }
            const uint32_t bco = ((uint32_t)(ks * 32) + b_kb) ^ lxor;
            #pragma unroll
            for (int ng = 0; ng < 2; ng++) {
                uint32_t Bh[4], Bl[4];
                ldsm4(Bh, bBase + ng * 2048 + bco);
                ldsm4(Bl, bBase + 16384 + ng * 2048 + bco);
                #pragma unroll
                for (int mf = 0; mf < 4; mf++) {
                    float* a0 = acc[mf][ng * 2];
                    float* a1 = acc[mf][ng * 2 + 1];
                    mma16816(a0, Ahi[mf], Bh);
                    mma16816(a0, Ahi[mf], Bl);
                    mma16816(a0, Alo[mf], Bh);
                    mma16816(a1, Ahi[mf], Bh + 2);
                    mma16816(a1, Ahi[mf], Bl + 2);
                    mma16816(a1, Alo[mf], Bh + 2);
                }
            }
        }
        __syncthreads();
    }

    // ---- fused epilogue: write g_fuse + RA(fuse) bins ----
    float* bins = (float*)smem;                    // 41*129 floats = 21156 B
    int*   slb  = (int*)(smem + 21248);            // 128 labels
    for (int i = tid; i < NCLS * 129; i += 256) bins[i] = 0.f;
    if (tid < 128) {
        int pp = p0 + tid;
        int yy = pp / WW;
        int xx = pp - yy * WW;
        slb[tid] = label[(size_t)b * 896 * 896 + (size_t)(4 * yy) * 896 + 4 * xx];
    }
    __syncthreads();

    float* fb = g_fuse + (size_t)b * CH * HW;
    const int prl = wm * 64 + (lane >> 2);         // pixel-in-block (row 0)
    const int oc0 = wn * 32 + (lane & 3) * 2;
    #pragma unroll
    for (int mf = 0; mf < 4; mf++) {
        const int px0 = prl + mf * 16;
        const int la  = slb[px0];
        const int lb2 = slb[px0 + 8];
        #pragma unroll
        for (int nf = 0; nf < 4; nf++) {
            const int oc = oc0 + nf * 8;
            float v0 = acc[mf][nf][0], v1 = acc[mf][nf][1];
            float v2 = acc[mf][nf][2], v3 = acc[mf][nf][3];
            fb[(size_t)oc * HW + p0 + px0]           = v0;
            fb[(size_t)(oc + 1) * HW + p0 + px0]     = v1;
            fb[(size_t)oc * HW + p0 + px0 + 8]       = v2;
            fb[(size_t)(oc + 1) * HW + p0 + px0 + 8] = v3;
            atomicAdd(&bins[la * 129 + oc], v0);
            atomicAdd(&bins[la * 129 + oc + 1], v1);
            atomicAdd(&bins[lb2 * 129 + oc], v2);
            atomicAdd(&bins[lb2 * 129 + oc + 1], v3);
        }
    }
    __syncthreads();
    for (int i = tid; i < NCLS * CH; i += 256) {
        int k = i >> 7;
        int c = i & 127;
        atomicAdd(&g_sum_f[((size_t)b * NCLS + k) * CH + c], bins[k * 129 + c]);
    }
}

// ---------------- final: out = fuse*scale_f + d*scale_d ----------------
__global__ void final_kernel(const float* __restrict__ dd, float* __restrict__ out) {
    int idx = blockIdx.x * 256 + threadIdx.x;
    const int n4 = BATCH * CH * HW / 4;
    if (idx >= n4) return;
    int i = idx * 4;
    int bc = i / HW;
    int b = bc >> 7;
    int c = bc & (CH - 1);
    float sd = g_scale[b * CH + c];
    float sf = g_scale[(BATCH + b) * CH + c];
    float4 dv = *reinterpret_cast<const float4*>(dd + i);
    float4 fv = *reinterpret_cast<const float4*>(g_fuse + i);
    float4 o;
    o.x = fv.x * sf + dv.x * sd;
    o.y = fv.y * sf + dv.y * sd;
    o.z = fv.z * sf + dv.z * sd;
    o.w = fv.w * sf + dv.w * sd;
    *reinterpret_cast<float4*>(out + i) = o;
}

// ---------------- launcher ----------------
extern "C" void kernel_launch(void* const* d_in, const int* in_sizes, int n_in,
                              void* d_out, int out_size) {
    const float* r      = (const float*)d_in[0];
    const float* d      = (const float*)d_in[1];
    const int*   label  = (const int*)  d_in[2];
    const float* w_fuse = (const float*)d_in[3];
    const float* w1_d   = (const float*)d_in[4];
    const float* w2_d   = (const float*)d_in[5];
    const float* w1_f   = (const float*)d_in[6];
    const float* w2_f   = (const float*)d_in[7];
    float* out = (float*)d_out;

    static int smem_set = 0;
    if (!smem_set) {
        cudaFuncSetAttribute(conv_mma_kernel, cudaFuncAttributeMaxDynamicSharedMemorySize, CONV_SMEM);
        smem_set = 1;
    }

    const int n4 = BATCH * CH * HW / 4;

    zero_kernel<<<(BATCH * NCLS * CH + 255) / 256, 256>>>();                       // 1
    wprep_kernel<<<(36 * 2 * CH * 64 + 255) / 256, 256>>>(w_fuse);                 // 2
    prep_ra_kernel<<<dim3(HW / 1024, BATCH, 4), 256>>>(r, d, label);               // 3
    conv_mma_kernel<<<dim3(HW / 128, BATCH), 256, CONV_SMEM>>>(label);             // 4
    ra_finalize_kernel<<<2 * BATCH, CH>>>(w1_d, w2_d, w1_f, w2_f);                 // 5
    final_kernel<<<(n4 + 255) / 256, 256>>>(d, out);                               // 6
}